// round 10
// baseline (speedup 1.0000x reference)
#include <cuda_runtime.h>
#include <math.h>
#include <math_constants.h>

#define BATCH 4
#define DIM 256
#define IMG 32
#define NPOS 1024
#define HEADS 8
#define DHEAD 64
#define INNER 512
#define BH 32
#define SCALE 0.125f

// ---------------- scratch (device globals; no allocations) ----------------
static __device__ float d_xt[BATCH * DIM * NPOS];
static __device__ float d_xattn[BATCH * 2 * NPOS];
static __device__ float d_qm[BH * NPOS * 2];
static __device__ float d_km[BH * NPOS * 2];
static __device__ float d_mmax[BH * NPOS];
static __device__ float d_msum[BH * NPOS];
static __device__ int   d_top4[BH * NPOS * 4];
static __device__ float d_y[3 * BATCH * DIM * NPOS];
static __device__ float d_qh[BH * NPOS * DHEAD];
static __device__ float d_kh[BH * NPOS * DHEAD];
static __device__ float d_vh[BH * NPOS * DHEAD];
static __device__ float d_ao[BATCH * NPOS * INNER];

#define YSTRIDE (BATCH * DIM * NPOS)

// ---------------- packed f32x2 helpers ----------------
typedef unsigned long long u64r;
__device__ __forceinline__ u64r pk2(float lo, float hi) {
    u64r r; asm("mov.b64 %0, {%1, %2};" : "=l"(r) : "f"(lo), "f"(hi)); return r;
}
__device__ __forceinline__ void upk2(u64r v, float& lo, float& hi) {
    asm("mov.b64 {%0, %1}, %2;" : "=f"(lo), "=f"(hi) : "l"(v));
}
__device__ __forceinline__ void ffma2(u64r& d, u64r a, u64r b) {
    asm("fma.rn.f32x2 %0, %1, %2, %0;" : "+l"(d) : "l"(a), "l"(b));
}
__device__ __forceinline__ u64r fmul2(u64r a, u64r b) {
    u64r r; asm("mul.rn.f32x2 %0, %1, %2;" : "=l"(r) : "l"(a), "l"(b)); return r;
}

__device__ __forceinline__ float mask_logit(float qm0, float qm1, float km0, float km1) {
    return __fmul_rn(__fadd_rn(__fmul_rn(qm0, km0), __fmul_rn(qm1, km1)), SCALE);
}

// strict total order: value desc, index asc (lax.top_k tie-break)
__device__ __forceinline__ bool topgt(float v1, int j1, float v2, int j2) {
    return v1 > v2 || (v1 == v2 && j1 < j2);
}
__device__ __forceinline__ void ce_keepmax(float& va, int& ia, float vb, int ib) {
    bool t = topgt(vb, ib, va, ia);
    va = t ? vb : va; ia = t ? ib : ia;
}
__device__ __forceinline__ void ce_sort(float& va, int& ia, float& vb, int& ib) {
    bool t = topgt(vb, ib, va, ia);
    float v = t ? vb : va; int i = t ? ib : ia;
    vb = t ? va : vb; ib = t ? ia : ib;
    va = v; ia = i;
}

// ---------------- kernel 0: transpose ----------------
__global__ void k_transpose(const float* __restrict__ x) {
    __shared__ float tile[32][33];
    int b = blockIdx.z;
    int p0 = blockIdx.x * 32, c0 = blockIdx.y * 32;
    int tx = threadIdx.x, ty = threadIdx.y;
    #pragma unroll
    for (int r = 0; r < 32; r += 8)
        tile[ty + r][tx] = x[(b * NPOS + p0 + ty + r) * DIM + c0 + tx];
    __syncthreads();
    #pragma unroll
    for (int r = 0; r < 32; r += 8)
        d_xt[(b * DIM + c0 + ty + r) * NPOS + p0 + tx] = tile[tx][ty + r];
}

// ---------------- kernel 1: channel mean/max ----------------
__global__ void k_meanmax(const float* __restrict__ x) {
    int bp = blockIdx.x;
    int b = bp >> 10, p = bp & 1023;
    int tid = threadIdx.x;
    float v = x[(b * NPOS + p) * DIM + tid];
    __shared__ float ss[256], sm[256];
    ss[tid] = v; sm[tid] = v;
    __syncthreads();
    for (int s = 128; s > 0; s >>= 1) {
        if (tid < s) { ss[tid] += ss[tid + s]; sm[tid] = fmaxf(sm[tid], sm[tid + s]); }
        __syncthreads();
    }
    if (tid == 0) {
        d_xattn[b * 2 * NPOS + p] = ss[0] * (1.f / 256.f);
        d_xattn[b * 2 * NPOS + NPOS + p] = sm[0];
    }
}

// ---------------- kernel 2: mask 3x3 convs ----------------
__global__ void k_maskconv(const float* __restrict__ qmw, const float* __restrict__ qmb,
                           const float* __restrict__ kmw, const float* __restrict__ kmb) {
    int idx = blockIdx.x * 256 + threadIdx.x;
    int b = idx >> 14;
    int rem = idx & 16383;
    int oc = rem >> 10;
    int p = rem & 1023;
    int py = p >> 5, px = p & 31;
    float aq = 0.f, ak = 0.f;
    #pragma unroll
    for (int ic = 0; ic < 2; ic++) {
        const float* xa = &d_xattn[(b * 2 + ic) * NPOS];
        #pragma unroll
        for (int ky = 0; ky < 3; ky++) {
            int iy = py + ky - 1;
            if ((unsigned)iy >= 32u) continue;
            #pragma unroll
            for (int kx = 0; kx < 3; kx++) {
                int ix = px + kx - 1;
                if ((unsigned)ix >= 32u) continue;
                float xv = xa[iy * 32 + ix];
                aq = fmaf(xv, qmw[((oc * 2 + ic) * 3 + ky) * 3 + kx], aq);
                ak = fmaf(xv, kmw[((oc * 2 + ic) * 3 + ky) * 3 + kx], ak);
            }
        }
    }
    aq += qmb[oc]; ak += kmb[oc];
    int h = oc >> 1, dd = oc & 1;
    d_qm[((b * HEADS + h) * NPOS + p) * 2 + dd] = aq;
    d_km[((b * HEADS + h) * NPOS + p) * 2 + dd] = ak;
}

// ---------------- kernel 3: mask stats + top-4 (two half-warps per row) ----------------
// block = 512 threads (16 warps); warps 2r,2r+1 handle row r (8 rows/block).
__global__ void k_masktop() {
    int tid = threadIdx.x;
    int wid = tid >> 5, lane = tid & 31;
    int r = wid >> 1, half = wid & 1;
    int row0 = blockIdx.x * 8;
    int bh = row0 >> 10;
    __shared__ float2 km2[NPOS];
    const float2* kmsrc = (const float2*)&d_km[bh * NPOS * 2];
    #pragma unroll
    for (int t = 0; t < 2; t++) km2[t * 512 + tid] = kmsrc[t * 512 + tid];
    __syncthreads();

    int row = row0 + r;
    float2 q2 = ((const float2*)d_qm)[row];

    float v0 = -CUDART_INF_F, v1 = -CUDART_INF_F, v2 = -CUDART_INF_F, v3 = -CUDART_INF_F;
    int j0i = 0x7fffffff, j1i = 0x7fffffff, j2i = 0x7fffffff, j3i = 0x7fffffff;

    // streaming insert: per-lane j strictly increases -> plain l > v test is the
    // (desc value, asc index) order (ties keep older/lower index).
    #pragma unroll
    for (int t = 0; t < 16; t++) {
        int j = t * 64 + half * 32 + lane;
        float2 k2 = km2[j];
        float l = mask_logit(q2.x, q2.y, k2.x, k2.y);
        bool g0 = l > v0;
        bool g1 = l > v1;
        bool g2 = l > v2;
        bool g3 = l > v3;
        float nv3 = g3 ? (g2 ? v2 : l) : v3; int nj3 = g3 ? (g2 ? j2i : j) : j3i;
        float nv2 = g2 ? (g1 ? v1 : l) : v2; int nj2 = g2 ? (g1 ? j1i : j) : j2i;
        float nv1 = g1 ? (g0 ? v0 : l) : v1; int nj1 = g1 ? (g0 ? j0i : j) : j1i;
        float nv0 = g0 ? l : v0;             int nj0 = g0 ? j : j0i;
        v0 = nv0; v1 = nv1; v2 = nv2; v3 = nv3;
        j0i = nj0; j1i = nj1; j2i = nj2; j3i = nj3;
    }

    // intra-warp butterfly merge (full tie-break comparator)
    #pragma unroll
    for (int off = 16; off > 0; off >>= 1) {
        float o0 = __shfl_xor_sync(0xffffffffu, v0, off);
        float o1 = __shfl_xor_sync(0xffffffffu, v1, off);
        float o2 = __shfl_xor_sync(0xffffffffu, v2, off);
        float o3 = __shfl_xor_sync(0xffffffffu, v3, off);
        int p0 = __shfl_xor_sync(0xffffffffu, j0i, off);
        int p1 = __shfl_xor_sync(0xffffffffu, j1i, off);
        int p2 = __shfl_xor_sync(0xffffffffu, j2i, off);
        int p3 = __shfl_xor_sync(0xffffffffu, j3i, off);
        ce_keepmax(v0, j0i, o3, p3);
        ce_keepmax(v1, j1i, o2, p2);
        ce_keepmax(v2, j2i, o1, p1);
        ce_keepmax(v3, j3i, o0, p0);
        ce_sort(v0, j0i, v2, j2i);
        ce_sort(v1, j1i, v3, j3i);
        ce_sort(v0, j0i, v1, j1i);
        ce_sort(v2, j2i, v3, j3i);
    }

    __shared__ float wv[16][4];
    __shared__ int   wj[16][4];
    if (lane == 0) {
        wv[wid][0] = v0; wv[wid][1] = v1; wv[wid][2] = v2; wv[wid][3] = v3;
        wj[wid][0] = j0i; wj[wid][1] = j1i; wj[wid][2] = j2i; wj[wid][3] = j3i;
    }
    __syncthreads();

    __shared__ float s_m[8];
    __shared__ int   s_fin[8][4];
    if (tid < 8) {
        int rr = tid;
        float a0 = wv[2 * rr][0], a1 = wv[2 * rr][1], a2 = wv[2 * rr][2], a3 = wv[2 * rr][3];
        int   c0 = wj[2 * rr][0], c1 = wj[2 * rr][1], c2 = wj[2 * rr][2], c3 = wj[2 * rr][3];
        float b0 = wv[2 * rr + 1][0], b1 = wv[2 * rr + 1][1], b2 = wv[2 * rr + 1][2], b3 = wv[2 * rr + 1][3];
        int   e0 = wj[2 * rr + 1][0], e1 = wj[2 * rr + 1][1], e2 = wj[2 * rr + 1][2], e3 = wj[2 * rr + 1][3];
        ce_keepmax(a0, c0, b3, e3);
        ce_keepmax(a1, c1, b2, e2);
        ce_keepmax(a2, c2, b1, e1);
        ce_keepmax(a3, c3, b0, e0);
        ce_sort(a0, c0, a2, c2);
        ce_sort(a1, c1, a3, c3);
        ce_sort(a0, c0, a1, c1);
        ce_sort(a2, c2, a3, c3);
        s_m[rr] = a0;
        s_fin[rr][0] = c0; s_fin[rr][1] = c1; s_fin[rr][2] = c2; s_fin[rr][3] = c3;
    }
    __syncthreads();

    float m = s_m[r];
    float s = 0.f;
    #pragma unroll
    for (int t = 0; t < 16; t++) {
        int j = t * 64 + half * 32 + lane;
        float2 k2 = km2[j];
        float l = mask_logit(q2.x, q2.y, k2.x, k2.y);
        s += __expf(l - m);
    }
    #pragma unroll
    for (int off = 16; off > 0; off >>= 1) s += __shfl_xor_sync(0xffffffffu, s, off);
    __shared__ float ps[16];
    if (lane == 0) ps[wid] = s;
    __syncthreads();
    if (tid < 8) {
        int rr = tid;
        int grow = row0 + rr;
        d_mmax[grow] = s_m[rr];
        d_msum[grow] = ps[2 * rr] + ps[2 * rr + 1];
        d_top4[grow * 4 + 0] = s_fin[rr][0];
        d_top4[grow * 4 + 1] = s_fin[rr][1];
        d_top4[grow * 4 + 2] = s_fin[rr][2];
        d_top4[grow * 4 + 3] = s_fin[rr][3];
    }
}

// ---------------- fused depthwise conv + BN (batch stats) + GELU ----------------
// grid (256, 3) = (channel, branch); block 256. One block owns all 4 batches of
// one channel -> computes conv, BN batch stats, normalize + exact GELU in one pass.
__global__ void k_sepconv(const float* __restrict__ w0, const float* __restrict__ b0,
                          const float* __restrict__ g0, const float* __restrict__ be0,
                          const float* __restrict__ w1, const float* __restrict__ b1,
                          const float* __restrict__ g1, const float* __restrict__ be1,
                          const float* __restrict__ w2, const float* __restrict__ b2,
                          const float* __restrict__ g2, const float* __restrict__ be2) {
    int c = blockIdx.x, br = blockIdx.y;
    const float* dw  = (br == 0) ? w0 : (br == 1) ? w1 : w2;
    const float* db  = (br == 0) ? b0 : (br == 1) ? b1 : b2;
    const float* gg  = (br == 0) ? g0 : (br == 1) ? g1 : g2;
    const float* bb  = (br == 0) ? be0 : (br == 1) ? be1 : be2;
    int tid = threadIdx.x;
    int lane = tid & 31, wid = tid >> 5;

    __shared__ float xs[BATCH][NPOS];
    __shared__ float w[9];
    __shared__ float bias;
    #pragma unroll
    for (int b = 0; b < BATCH; b++) {
        const float* src = &d_xt[(b * DIM + c) * NPOS];
        #pragma unroll
        for (int t = 0; t < 4; t++) xs[b][t * 256 + tid] = src[t * 256 + tid];
    }
    if (tid < 9) w[tid] = dw[c * 9 + tid];
    if (tid == 9) bias = db[c];
    __syncthreads();

    // conv into registers + accumulate stats (same per-thread order as old bnstats: b outer, t inner)
    float vv[16];
    float s1 = 0.f, s2 = 0.f;
    #pragma unroll
    for (int b = 0; b < BATCH; b++) {
        #pragma unroll
        for (int t = 0; t < 4; t++) {
            int p = t * 256 + tid;
            int py = p >> 5, px = p & 31;
            float a = 0.f;
            #pragma unroll
            for (int ky = 0; ky < 3; ky++) {
                int iy = py + ky - 1;
                if ((unsigned)iy >= 32u) continue;
                #pragma unroll
                for (int kx = 0; kx < 3; kx++) {
                    int ix = px + kx - 1;
                    if ((unsigned)ix >= 32u) continue;
                    a = fmaf(xs[b][iy * 32 + ix], w[ky * 3 + kx], a);
                }
            }
            float v = a + bias;
            vv[b * 4 + t] = v;
            s1 += v;
            s2 = fmaf(v, v, s2);
        }
    }

    // block reduce stats
    #pragma unroll
    for (int off = 16; off > 0; off >>= 1) {
        s1 += __shfl_xor_sync(0xffffffffu, s1, off);
        s2 += __shfl_xor_sync(0xffffffffu, s2, off);
    }
    __shared__ float rs1[8], rs2[8];
    if (lane == 0) { rs1[wid] = s1; rs2[wid] = s2; }
    __syncthreads();
    __shared__ float s_mu, s_var;
    if (tid == 0) {
        float a = 0.f, q = 0.f;
        #pragma unroll
        for (int i = 0; i < 8; i++) { a += rs1[i]; q += rs2[i]; }
        float mu = a * (1.f / 4096.f);
        float var = q * (1.f / 4096.f) - mu * mu;
        s_mu = mu;
        s_var = fmaxf(var, 0.f);
    }
    __syncthreads();

    float mu = s_mu, var = s_var;
    float gv = gg[c], bv = bb[c];
    float* dst = &d_y[br * YSTRIDE + c * NPOS];   // + b*DIM*NPOS per batch
    #pragma unroll
    for (int b = 0; b < BATCH; b++) {
        #pragma unroll
        for (int t = 0; t < 4; t++) {
            int p = t * 256 + tid;
            float nv = (vv[b * 4 + t] - mu) / sqrtf(var + 1e-5f) * gv + bv;
            float o = 0.5f * nv * (1.0f + erff(nv * 0.70710678118654752f));
            dst[b * DIM * NPOS + p] = o;
        }
    }
}

// ---------------- pointwise 1x1 conv GEMM (FFMA2) ----------------
__global__ void k_pwgemm(const float* __restrict__ w0, const float* __restrict__ bb0,
                         const float* __restrict__ w1, const float* __restrict__ bb1,
                         const float* __restrict__ w2, const float* __restrict__ bb2) {
    __shared__ float As[32][68];
    __shared__ float Ws[32][68];
    int br = blockIdx.z >> 2;
    int b = blockIdx.z & 3;
    const float* w = (br == 0) ? w0 : (br == 1) ? w1 : w2;
    const float* bias = (br == 0) ? bb0 : (br == 1) ? bb1 : bb2;
    float* out = (br == 0) ? d_qh : (br == 1) ? d_kh : d_vh;
    int oc0 = blockIdx.y * 64;
    int i0 = blockIdx.x * 64;
    int tid = threadIdx.x;
    int ty = tid >> 4, tx = tid & 15;
    u64r accp[4][2];
    #pragma unroll
    for (int r = 0; r < 4; r++) { accp[r][0] = 0ull; accp[r][1] = 0ull; }
    for (int c0 = 0; c0 < DIM; c0 += 32) {
        #pragma unroll
        for (int t = 0; t < 8; t++) {
            int idx = tid + t * 256;
            int ii = idx & 63, cc = idx >> 6;
            As[cc][ii] = d_y[br * YSTRIDE + (b * DIM + c0 + cc) * NPOS + i0 + ii];
        }
        #pragma unroll
        for (int t = 0; t < 8; t++) {
            int idx = tid + t * 256;
            int cc = idx & 31, o = idx >> 5;
            Ws[cc][o] = w[(oc0 + o) * DIM + c0 + cc];
        }
        __syncthreads();
        #pragma unroll
        for (int cc = 0; cc < 32; cc++) {
            u64r a01 = *(const u64r*)&As[cc][tx * 4];
            u64r a23 = *(const u64r*)&As[cc][tx * 4 + 2];
            #pragma unroll
            for (int r = 0; r < 4; r++) {
                float wv = Ws[cc][ty * 4 + r];
                u64r ww = pk2(wv, wv);
                ffma2(accp[r][0], a01, ww);
                ffma2(accp[r][1], a23, ww);
            }
        }
        __syncthreads();
    }
    #pragma unroll
    for (int r = 0; r < 4; r++) {
        int oc = oc0 + ty * 4 + r;
        int h = oc >> 6, dd = oc & 63;
        float bbv = bias[oc];
        float c0v, c1v, c2v, c3v;
        upk2(accp[r][0], c0v, c1v);
        upk2(accp[r][1], c2v, c3v);
        float cv[4] = {c0v, c1v, c2v, c3v};
        #pragma unroll
        for (int cq = 0; cq < 4; cq++) {
            int ii = i0 + tx * 4 + cq;
            out[((b * HEADS + h) * NPOS + ii) * DHEAD + dd] = cv[cq] + bbv;
        }
    }
}

// ---------------- fused attention (FFMA2): QK*mask -> online softmax -> PV ----------------
__global__ void k_attn() {
    __shared__ float Qs[64][68];    // [dd][ii]
    __shared__ float Ks[64][33];    // [dd][jj]
    __shared__ float Vs[32][68];    // [jj][dd]
    __shared__ float Es[32][68];    // [jj][ii]
    __shared__ float s_qm[64][2];
    __shared__ float s_mmax[64];
    __shared__ float s_minv[64];
    __shared__ int   s_top[64][4];

    int i0 = blockIdx.x * 64;
    int bh = blockIdx.y;
    int tid = threadIdx.x;
    int ty = tid >> 4, tx = tid & 15;

    #pragma unroll
    for (int t = 0; t < 16; t++) {
        int idx = tid + t * 256;
        int dd = idx & 63, ii = idx >> 6;
        Qs[dd][ii] = d_qh[(bh * NPOS + i0 + ii) * DHEAD + dd];
    }
    if (tid < 64) {
        int ig = bh * NPOS + i0 + tid;
        s_qm[tid][0] = d_qm[ig * 2];
        s_qm[tid][1] = d_qm[ig * 2 + 1];
        s_mmax[tid] = d_mmax[ig];
        s_minv[tid] = 1.0f / d_msum[ig];
        #pragma unroll
        for (int t = 0; t < 4; t++) s_top[tid][t] = d_top4[ig * 4 + t];
    }
    __syncthreads();

    float run_max[4], run_sum[4];
    #pragma unroll
    for (int r = 0; r < 4; r++) { run_max[r] = -CUDART_INF_F; run_sum[r] = 0.f; }
    u64r accp[2][4];
    #pragma unroll
    for (int c = 0; c < 4; c++) { accp[0][c] = 0ull; accp[1][c] = 0ull; }

    for (int j0 = 0; j0 < NPOS; j0 += 32) {
        #pragma unroll
        for (int t = 0; t < 8; t++) {
            int idx = tid + t * 256;
            int dd = idx & 63, jj = idx >> 6;
            Ks[dd][jj] = d_kh[(bh * NPOS + j0 + jj) * DHEAD + dd];
            Vs[jj][dd] = d_vh[(bh * NPOS + j0 + jj) * DHEAD + dd];
        }
        __syncthreads();

        u64r q00 = 0ull, q01 = 0ull, q10 = 0ull, q11 = 0ull;
        #pragma unroll
        for (int dd = 0; dd < 64; dd++) {
            u64r a01 = *(const u64r*)&Qs[dd][ty * 4];
            u64r a23 = *(const u64r*)&Qs[dd][ty * 4 + 2];
            float b0 = Ks[dd][tx * 2];
            float b1 = Ks[dd][tx * 2 + 1];
            u64r bb0 = pk2(b0, b0);
            u64r bb1 = pk2(b1, b1);
            ffma2(q00, a01, bb0);
            ffma2(q01, a01, bb1);
            ffma2(q10, a23, bb0);
            ffma2(q11, a23, bb1);
        }
        float sv[8];
        upk2(q00, sv[0], sv[2]);
        upk2(q01, sv[1], sv[3]);
        upk2(q10, sv[4], sv[6]);
        upk2(q11, sv[5], sv[7]);

        #pragma unroll
        for (int cq = 0; cq < 2; cq++) {
            int jg = j0 + tx * 2 + cq;
            float2 k2 = ((const float2*)d_km)[bh * NPOS + jg];
            #pragma unroll
            for (int r = 0; r < 4; r++) {
                int il = ty * 4 + r;
                float ml = mask_logit(s_qm[il][0], s_qm[il][1], k2.x, k2.y);
                float dprob = __expf(ml - s_mmax[il]) * s_minv[il];
                float oneh = (jg == s_top[il][0] || jg == s_top[il][1] ||
                              jg == s_top[il][2] || jg == s_top[il][3]) ? 1.0f : -100000.0f;
                float maskv = __fadd_rn(__fadd_rn(oneh, -dprob), dprob);
                sv[r * 2 + cq] = __fmul_rn(__fmul_rn(sv[r * 2 + cq], SCALE), maskv);
            }
        }

        float tm[4];
        #pragma unroll
        for (int r = 0; r < 4; r++) tm[r] = fmaxf(sv[r * 2], sv[r * 2 + 1]);
        #pragma unroll
        for (int off = 1; off < 16; off <<= 1) {
            #pragma unroll
            for (int r = 0; r < 4; r++)
                tm[r] = fmaxf(tm[r], __shfl_xor_sync(0xffffffffu, tm[r], off));
        }

        float fr[4];
        #pragma unroll
        for (int r = 0; r < 4; r++) {
            float nm = fmaxf(run_max[r], tm[r]);
            float f = __expf(run_max[r] - nm);
            run_max[r] = nm;
            fr[r] = f;
            float e0 = __expf(sv[r * 2] - nm);
            float e1 = __expf(sv[r * 2 + 1] - nm);
            run_sum[r] = run_sum[r] * f + e0 + e1;
            Es[tx * 2][ty * 4 + r]     = e0;
            Es[tx * 2 + 1][ty * 4 + r] = e1;
        }
        {
            u64r ff0 = pk2(fr[0], fr[1]);
            u64r ff1 = pk2(fr[2], fr[3]);
            #pragma unroll
            for (int c = 0; c < 4; c++) {
                accp[0][c] = fmul2(accp[0][c], ff0);
                accp[1][c] = fmul2(accp[1][c], ff1);
            }
        }
        __syncthreads();

        #pragma unroll
        for (int jj = 0; jj < 32; jj++) {
            u64r a01 = *(const u64r*)&Es[jj][ty * 4];
            u64r a23 = *(const u64r*)&Es[jj][ty * 4 + 2];
            #pragma unroll
            for (int c = 0; c < 4; c++) {
                float bvv = Vs[jj][tx * 4 + c];
                u64r bb = pk2(bvv, bvv);
                ffma2(accp[0][c], a01, bb);
                ffma2(accp[1][c], a23, bb);
            }
        }
        __syncthreads();
    }

    #pragma unroll
    for (int off = 1; off < 16; off <<= 1) {
        #pragma unroll
        for (int r = 0; r < 4; r++)
            run_sum[r] += __shfl_xor_sync(0xffffffffu, run_sum[r], off);
    }
    float ov[4][4];
    #pragma unroll
    for (int rp = 0; rp < 2; rp++)
        #pragma unroll
        for (int c = 0; c < 4; c++)
            upk2(accp[rp][c], ov[2 * rp][c], ov[2 * rp + 1][c]);

    int b = bh >> 3, h = bh & 7;
    #pragma unroll
    for (int r = 0; r < 4; r++) {
        int ii = i0 + ty * 4 + r;
        float inv = 1.0f / run_sum[r];
        float4 st;
        #pragma unroll
        for (int c = 0; c < 4; c++) ((float*)&st)[c] = ov[r][c] * inv;
        *(float4*)&d_ao[((size_t)(b * NPOS + ii)) * INNER + h * DHEAD + tx * 4] = st;
    }
}

// ---------------- output GEMM (FFMA2) ----------------
__global__ void k_out(const float* __restrict__ w, const float* __restrict__ ob, float* __restrict__ out) {
    __shared__ float As[32][68];
    __shared__ float Ws[32][68];
    int o0 = blockIdx.x * 64;
    int bi0 = blockIdx.y * 64;
    int tid = threadIdx.x;
    int ty = tid >> 4, tx = tid & 15;
    u64r accp[4][2];
    #pragma unroll
    for (int r = 0; r < 4; r++) { accp[r][0] = 0ull; accp[r][1] = 0ull; }
    for (int c0 = 0; c0 < INNER; c0 += 32) {
        #pragma unroll
        for (int t = 0; t < 8; t++) {
            int idx = tid + t * 256;
            int cc = idx & 31, ii = idx >> 5;
            As[cc][ii] = d_ao[(size_t)(bi0 + ii) * INNER + c0 + cc];
        }
        #pragma unroll
        for (int t = 0; t < 8; t++) {
            int idx = tid + t * 256;
            int cc = idx & 31, o = idx >> 5;
            Ws[cc][o] = w[(o0 + o) * INNER + c0 + cc];
        }
        __syncthreads();
        #pragma unroll
        for (int cc = 0; cc < 32; cc++) {
            u64r a01 = *(const u64r*)&As[cc][ty * 4];
            u64r a23 = *(const u64r*)&As[cc][ty * 4 + 2];
            #pragma unroll
            for (int r = 0; r < 4; r++) {
                float wv = Ws[cc][tx * 4 + r];
                u64r ww = pk2(wv, wv);
                ffma2(accp[r][0], a01, ww);
                ffma2(accp[r][1], a23, ww);
            }
        }
        __syncthreads();
    }
    #pragma unroll
    for (int r = 0; r < 4; r++) {
        int o = o0 + tx * 4 + r;
        float b0v, b1v, b2v, b3v;
        upk2(accp[r][0], b0v, b1v);
        upk2(accp[r][1], b2v, b3v);
        float bv[4] = {b0v, b1v, b2v, b3v};
        float obv = ob[o];
        #pragma unroll
        for (int q = 0; q < 4; q++) {
            int bi = bi0 + ty * 4 + q;
            out[(size_t)bi * DIM + o] = bv[q] + obv;
        }
    }
}

// ---------------- launch ----------------
extern "C" void kernel_launch(void* const* d_in, const int* in_sizes, int n_in,
                              void* d_out, int out_size) {
    const float* x     = (const float*)d_in[0];
    const float* qd_w  = (const float*)d_in[1];
    const float* qd_b  = (const float*)d_in[2];
    const float* q_g   = (const float*)d_in[3];
    const float* q_be  = (const float*)d_in[4];
    const float* qp_w  = (const float*)d_in[5];
    const float* qp_b  = (const float*)d_in[6];
    const float* qm_w  = (const float*)d_in[7];
    const float* qm_b  = (const float*)d_in[8];
    const float* kd_w  = (const float*)d_in[9];
    const float* kd_b  = (const float*)d_in[10];
    const float* k_g   = (const float*)d_in[11];
    const float* k_be  = (const float*)d_in[12];
    const float* kp_w  = (const float*)d_in[13];
    const float* kp_b  = (const float*)d_in[14];
    const float* km_w  = (const float*)d_in[15];
    const float* km_b  = (const float*)d_in[16];
    const float* vd_w  = (const float*)d_in[17];
    const float* vd_b  = (const float*)d_in[18];
    const float* v_g   = (const float*)d_in[19];
    const float* v_be  = (const float*)d_in[20];
    const float* vp_w  = (const float*)d_in[21];
    const float* vp_b  = (const float*)d_in[22];
    const float* out_w = (const float*)d_in[25];
    const float* out_b = (const float*)d_in[26];
    float* out = (float*)d_out;

    k_transpose<<<dim3(32, 8, 4), dim3(32, 8)>>>(x);
    k_meanmax<<<4096, 256>>>(x);
    k_maskconv<<<256, 256>>>(qm_w, qm_b, km_w, km_b);
    k_masktop<<<4096, 512>>>();

    k_sepconv<<<dim3(256, 3), 256>>>(qd_w, qd_b, q_g, q_be,
                                     kd_w, kd_b, k_g, k_be,
                                     vd_w, vd_b, v_g, v_be);
    k_pwgemm<<<dim3(16, 8, 12), 256>>>(qp_w, qp_b, kp_w, kp_b, vp_w, vp_b);

    k_attn<<<dim3(16, 32), 256>>>();
    k_out<<<dim3(4, 64), 256>>>(out_w, out_b, out);
}

// round 11
// speedup vs baseline: 1.0393x; 1.0393x over previous
#include <cuda_runtime.h>
#include <math.h>
#include <math_constants.h>

#define BATCH 4
#define DIM 256
#define IMG 32
#define NPOS 1024
#define HEADS 8
#define DHEAD 64
#define INNER 512
#define BH 32
#define SCALE 0.125f

// ---------------- scratch (device globals; no allocations) ----------------
static __device__ float d_xt[BATCH * DIM * NPOS];
static __device__ float d_xattn[BATCH * 2 * NPOS];
static __device__ float d_qm[BH * NPOS * 2];
static __device__ float d_km[BH * NPOS * 2];
static __device__ float d_mmax[BH * NPOS];
static __device__ float d_msum[BH * NPOS];
static __device__ int   d_top4[BH * NPOS * 4];
static __device__ float d_y[3 * BATCH * DIM * NPOS];
static __device__ float d_qh[BH * NPOS * DHEAD];
static __device__ float d_kh[BH * NPOS * DHEAD];
static __device__ float d_vh[BH * NPOS * DHEAD];
static __device__ float d_ao[BATCH * NPOS * INNER];

#define YSTRIDE (BATCH * DIM * NPOS)

// ---------------- packed f32x2 helpers ----------------
typedef unsigned long long u64r;
__device__ __forceinline__ u64r pk2(float lo, float hi) {
    u64r r; asm("mov.b64 %0, {%1, %2};" : "=l"(r) : "f"(lo), "f"(hi)); return r;
}
__device__ __forceinline__ void upk2(u64r v, float& lo, float& hi) {
    asm("mov.b64 {%0, %1}, %2;" : "=f"(lo), "=f"(hi) : "l"(v));
}
__device__ __forceinline__ void ffma2(u64r& d, u64r a, u64r b) {
    asm("fma.rn.f32x2 %0, %1, %2, %0;" : "+l"(d) : "l"(a), "l"(b));
}
__device__ __forceinline__ u64r fmul2(u64r a, u64r b) {
    u64r r; asm("mul.rn.f32x2 %0, %1, %2;" : "=l"(r) : "l"(a), "l"(b)); return r;
}

__device__ __forceinline__ float mask_logit(float qm0, float qm1, float km0, float km1) {
    return __fmul_rn(__fadd_rn(__fmul_rn(qm0, km0), __fmul_rn(qm1, km1)), SCALE);
}

// strict total order: value desc, index asc (lax.top_k tie-break)
__device__ __forceinline__ bool topgt(float v1, int j1, float v2, int j2) {
    return v1 > v2 || (v1 == v2 && j1 < j2);
}
__device__ __forceinline__ void ce_keepmax(float& va, int& ia, float vb, int ib) {
    bool t = topgt(vb, ib, va, ia);
    va = t ? vb : va; ia = t ? ib : ia;
}
__device__ __forceinline__ void ce_sort(float& va, int& ia, float& vb, int& ib) {
    bool t = topgt(vb, ib, va, ia);
    float v = t ? vb : va; int i = t ? ib : ia;
    vb = t ? va : vb; ib = t ? ia : ib;
    va = v; ia = i;
}

// ---------------- kernel 0: transpose ----------------
__global__ void k_transpose(const float* __restrict__ x) {
    __shared__ float tile[32][33];
    int b = blockIdx.z;
    int p0 = blockIdx.x * 32, c0 = blockIdx.y * 32;
    int tx = threadIdx.x, ty = threadIdx.y;
    #pragma unroll
    for (int r = 0; r < 32; r += 8)
        tile[ty + r][tx] = x[(b * NPOS + p0 + ty + r) * DIM + c0 + tx];
    __syncthreads();
    #pragma unroll
    for (int r = 0; r < 32; r += 8)
        d_xt[(b * DIM + c0 + ty + r) * NPOS + p0 + tx] = tile[tx][ty + r];
}

// ---------------- kernel 1: channel mean/max ----------------
__global__ void k_meanmax(const float* __restrict__ x) {
    int bp = blockIdx.x;
    int b = bp >> 10, p = bp & 1023;
    int tid = threadIdx.x;
    float v = x[(b * NPOS + p) * DIM + tid];
    __shared__ float ss[256], sm[256];
    ss[tid] = v; sm[tid] = v;
    __syncthreads();
    for (int s = 128; s > 0; s >>= 1) {
        if (tid < s) { ss[tid] += ss[tid + s]; sm[tid] = fmaxf(sm[tid], sm[tid + s]); }
        __syncthreads();
    }
    if (tid == 0) {
        d_xattn[b * 2 * NPOS + p] = ss[0] * (1.f / 256.f);
        d_xattn[b * 2 * NPOS + NPOS + p] = sm[0];
    }
}

// ---------------- kernel 2: mask 3x3 convs ----------------
__global__ void k_maskconv(const float* __restrict__ qmw, const float* __restrict__ qmb,
                           const float* __restrict__ kmw, const float* __restrict__ kmb) {
    int idx = blockIdx.x * 256 + threadIdx.x;
    int b = idx >> 14;
    int rem = idx & 16383;
    int oc = rem >> 10;
    int p = rem & 1023;
    int py = p >> 5, px = p & 31;
    float aq = 0.f, ak = 0.f;
    #pragma unroll
    for (int ic = 0; ic < 2; ic++) {
        const float* xa = &d_xattn[(b * 2 + ic) * NPOS];
        #pragma unroll
        for (int ky = 0; ky < 3; ky++) {
            int iy = py + ky - 1;
            if ((unsigned)iy >= 32u) continue;
            #pragma unroll
            for (int kx = 0; kx < 3; kx++) {
                int ix = px + kx - 1;
                if ((unsigned)ix >= 32u) continue;
                float xv = xa[iy * 32 + ix];
                aq = fmaf(xv, qmw[((oc * 2 + ic) * 3 + ky) * 3 + kx], aq);
                ak = fmaf(xv, kmw[((oc * 2 + ic) * 3 + ky) * 3 + kx], ak);
            }
        }
    }
    aq += qmb[oc]; ak += kmb[oc];
    int h = oc >> 1, dd = oc & 1;
    d_qm[((b * HEADS + h) * NPOS + p) * 2 + dd] = aq;
    d_km[((b * HEADS + h) * NPOS + p) * 2 + dd] = ak;
}

// ---------------- kernel 3: warp-per-row mask stats + top-4 ----------------
__global__ void k_masktop() {
    int tid = threadIdx.x;
    int w = tid >> 5, lane = tid & 31;
    int row0 = blockIdx.x * 8;
    int bh = row0 >> 10;
    __shared__ float2 km2[NPOS];
    const float2* kmsrc = (const float2*)&d_km[bh * NPOS * 2];
    #pragma unroll
    for (int t = 0; t < 4; t++) km2[t * 256 + tid] = kmsrc[t * 256 + tid];
    __syncthreads();

    int row = row0 + w;
    float2 q2 = ((const float2*)d_qm)[row];

    float v0 = -CUDART_INF_F, v1 = -CUDART_INF_F, v2 = -CUDART_INF_F, v3 = -CUDART_INF_F;
    int j0i = 0x7fffffff, j1i = 0x7fffffff, j2i = 0x7fffffff, j3i = 0x7fffffff;

    // streaming insert: per-lane j strictly increases, so the (desc value, asc index)
    // test against stored entries reduces to plain l > v (ties keep older/lower index).
    #pragma unroll
    for (int t = 0; t < 32; t++) {
        int j = t * 32 + lane;
        float2 k2 = km2[j];
        float l = mask_logit(q2.x, q2.y, k2.x, k2.y);
        bool g0 = l > v0;
        bool g1 = l > v1;
        bool g2 = l > v2;
        bool g3 = l > v3;
        float nv3 = g3 ? (g2 ? v2 : l) : v3; int nj3 = g3 ? (g2 ? j2i : j) : j3i;
        float nv2 = g2 ? (g1 ? v1 : l) : v2; int nj2 = g2 ? (g1 ? j1i : j) : j2i;
        float nv1 = g1 ? (g0 ? v0 : l) : v1; int nj1 = g1 ? (g0 ? j0i : j) : j1i;
        float nv0 = g0 ? l : v0;             int nj0 = g0 ? j : j0i;
        v0 = nv0; v1 = nv1; v2 = nv2; v3 = nv3;
        j0i = nj0; j1i = nj1; j2i = nj2; j3i = nj3;
    }

    // cross-lane merge: full tie-break order (indices arbitrary across lanes)
    #pragma unroll
    for (int off = 16; off > 0; off >>= 1) {
        float o0 = __shfl_xor_sync(0xffffffffu, v0, off);
        float o1 = __shfl_xor_sync(0xffffffffu, v1, off);
        float o2 = __shfl_xor_sync(0xffffffffu, v2, off);
        float o3 = __shfl_xor_sync(0xffffffffu, v3, off);
        int p0 = __shfl_xor_sync(0xffffffffu, j0i, off);
        int p1 = __shfl_xor_sync(0xffffffffu, j1i, off);
        int p2 = __shfl_xor_sync(0xffffffffu, j2i, off);
        int p3 = __shfl_xor_sync(0xffffffffu, j3i, off);
        ce_keepmax(v0, j0i, o3, p3);
        ce_keepmax(v1, j1i, o2, p2);
        ce_keepmax(v2, j2i, o1, p1);
        ce_keepmax(v3, j3i, o0, p0);
        ce_sort(v0, j0i, v2, j2i);
        ce_sort(v1, j1i, v3, j3i);
        ce_sort(v0, j0i, v1, j1i);
        ce_sort(v2, j2i, v3, j3i);
    }

    float m = v0;
    float s = 0.f;
    #pragma unroll
    for (int t = 0; t < 32; t++) {
        int j = t * 32 + lane;
        float2 k2 = km2[j];
        float l = mask_logit(q2.x, q2.y, k2.x, k2.y);
        s += __expf(l - m);
    }
    #pragma unroll
    for (int off = 16; off > 0; off >>= 1) s += __shfl_xor_sync(0xffffffffu, s, off);

    if (lane == 0) {
        d_mmax[row] = m;
        d_msum[row] = s;
        d_top4[row * 4 + 0] = j0i;
        d_top4[row * 4 + 1] = j1i;
        d_top4[row * 4 + 2] = j2i;
        d_top4[row * 4 + 3] = j3i;
    }
}

// ---------------- fused depthwise conv + BN (batch stats) + GELU ----------------
// grid (256, 3) = (channel, branch); block 256. One block owns all 4 batches of
// one channel -> computes conv, BN batch stats, normalize + exact GELU in one pass.
__global__ void k_sepconv(const float* __restrict__ w0, const float* __restrict__ b0,
                          const float* __restrict__ g0, const float* __restrict__ be0,
                          const float* __restrict__ w1, const float* __restrict__ b1,
                          const float* __restrict__ g1, const float* __restrict__ be1,
                          const float* __restrict__ w2, const float* __restrict__ b2,
                          const float* __restrict__ g2, const float* __restrict__ be2) {
    int c = blockIdx.x, br = blockIdx.y;
    const float* dw  = (br == 0) ? w0 : (br == 1) ? w1 : w2;
    const float* db  = (br == 0) ? b0 : (br == 1) ? b1 : b2;
    const float* gg  = (br == 0) ? g0 : (br == 1) ? g1 : g2;
    const float* bb  = (br == 0) ? be0 : (br == 1) ? be1 : be2;
    int tid = threadIdx.x;
    int lane = tid & 31, wid = tid >> 5;

    __shared__ float xs[BATCH][NPOS];
    __shared__ float w[9];
    __shared__ float bias;
    #pragma unroll
    for (int b = 0; b < BATCH; b++) {
        const float* src = &d_xt[(b * DIM + c) * NPOS];
        #pragma unroll
        for (int t = 0; t < 4; t++) xs[b][t * 256 + tid] = src[t * 256 + tid];
    }
    if (tid < 9) w[tid] = dw[c * 9 + tid];
    if (tid == 9) bias = db[c];
    __syncthreads();

    // conv into registers + accumulate stats
    float vv[16];
    float s1 = 0.f, s2 = 0.f;
    #pragma unroll
    for (int b = 0; b < BATCH; b++) {
        #pragma unroll
        for (int t = 0; t < 4; t++) {
            int p = t * 256 + tid;
            int py = p >> 5, px = p & 31;
            float a = 0.f;
            #pragma unroll
            for (int ky = 0; ky < 3; ky++) {
                int iy = py + ky - 1;
                if ((unsigned)iy >= 32u) continue;
                #pragma unroll
                for (int kx = 0; kx < 3; kx++) {
                    int ix = px + kx - 1;
                    if ((unsigned)ix >= 32u) continue;
                    a = fmaf(xs[b][iy * 32 + ix], w[ky * 3 + kx], a);
                }
            }
            float v = a + bias;
            vv[b * 4 + t] = v;
            s1 += v;
            s2 = fmaf(v, v, s2);
        }
    }

    // block reduce stats
    #pragma unroll
    for (int off = 16; off > 0; off >>= 1) {
        s1 += __shfl_xor_sync(0xffffffffu, s1, off);
        s2 += __shfl_xor_sync(0xffffffffu, s2, off);
    }
    __shared__ float rs1[8], rs2[8];
    if (lane == 0) { rs1[wid] = s1; rs2[wid] = s2; }
    __syncthreads();
    __shared__ float s_mu, s_var;
    if (tid == 0) {
        float a = 0.f, q = 0.f;
        #pragma unroll
        for (int i = 0; i < 8; i++) { a += rs1[i]; q += rs2[i]; }
        float mu = a * (1.f / 4096.f);
        float var = q * (1.f / 4096.f) - mu * mu;
        s_mu = mu;
        s_var = fmaxf(var, 0.f);
    }
    __syncthreads();

    float mu = s_mu, var = s_var;
    float gv = gg[c], bv = bb[c];
    float* dst = &d_y[br * YSTRIDE + c * NPOS];
    #pragma unroll
    for (int b = 0; b < BATCH; b++) {
        #pragma unroll
        for (int t = 0; t < 4; t++) {
            int p = t * 256 + tid;
            float nv = (vv[b * 4 + t] - mu) / sqrtf(var + 1e-5f) * gv + bv;
            float o = 0.5f * nv * (1.0f + erff(nv * 0.70710678118654752f));
            dst[b * DIM * NPOS + p] = o;
        }
    }
}

// ---------------- pointwise 1x1 conv GEMM (FFMA2) ----------------
__global__ void k_pwgemm(const float* __restrict__ w0, const float* __restrict__ bb0,
                         const float* __restrict__ w1, const float* __restrict__ bb1,
                         const float* __restrict__ w2, const float* __restrict__ bb2) {
    __shared__ float As[32][68];
    __shared__ float Ws[32][68];
    int br = blockIdx.z >> 2;
    int b = blockIdx.z & 3;
    const float* w = (br == 0) ? w0 : (br == 1) ? w1 : w2;
    const float* bias = (br == 0) ? bb0 : (br == 1) ? bb1 : bb2;
    float* out = (br == 0) ? d_qh : (br == 1) ? d_kh : d_vh;
    int oc0 = blockIdx.y * 64;
    int i0 = blockIdx.x * 64;
    int tid = threadIdx.x;
    int ty = tid >> 4, tx = tid & 15;
    u64r accp[4][2];
    #pragma unroll
    for (int r = 0; r < 4; r++) { accp[r][0] = 0ull; accp[r][1] = 0ull; }
    for (int c0 = 0; c0 < DIM; c0 += 32) {
        #pragma unroll
        for (int t = 0; t < 8; t++) {
            int idx = tid + t * 256;
            int ii = idx & 63, cc = idx >> 6;
            As[cc][ii] = d_y[br * YSTRIDE + (b * DIM + c0 + cc) * NPOS + i0 + ii];
        }
        #pragma unroll
        for (int t = 0; t < 8; t++) {
            int idx = tid + t * 256;
            int cc = idx & 31, o = idx >> 5;
            Ws[cc][o] = w[(oc0 + o) * DIM + c0 + cc];
        }
        __syncthreads();
        #pragma unroll
        for (int cc = 0; cc < 32; cc++) {
            u64r a01 = *(const u64r*)&As[cc][tx * 4];
            u64r a23 = *(const u64r*)&As[cc][tx * 4 + 2];
            #pragma unroll
            for (int r = 0; r < 4; r++) {
                float wv = Ws[cc][ty * 4 + r];
                u64r ww = pk2(wv, wv);
                ffma2(accp[r][0], a01, ww);
                ffma2(accp[r][1], a23, ww);
            }
        }
        __syncthreads();
    }
    #pragma unroll
    for (int r = 0; r < 4; r++) {
        int oc = oc0 + ty * 4 + r;
        int h = oc >> 6, dd = oc & 63;
        float bbv = bias[oc];
        float c0v, c1v, c2v, c3v;
        upk2(accp[r][0], c0v, c1v);
        upk2(accp[r][1], c2v, c3v);
        float cv[4] = {c0v, c1v, c2v, c3v};
        #pragma unroll
        for (int cq = 0; cq < 4; cq++) {
            int ii = i0 + tx * 4 + cq;
            out[((b * HEADS + h) * NPOS + ii) * DHEAD + dd] = cv[cq] + bbv;
        }
    }
}

// ---------------- fused attention (FFMA2): QK*mask -> online softmax -> PV ----------------
__global__ void k_attn() {
    __shared__ float Qs[64][68];    // [dd][ii]
    __shared__ float Ks[64][33];    // [dd][jj]
    __shared__ float Vs[32][68];    // [jj][dd]
    __shared__ float Es[32][68];    // [jj][ii]
    __shared__ float s_qm[64][2];
    __shared__ float s_mmax[64];
    __shared__ float s_minv[64];
    __shared__ int   s_top[64][4];

    int i0 = blockIdx.x * 64;
    int bh = blockIdx.y;
    int tid = threadIdx.x;
    int ty = tid >> 4, tx = tid & 15;

    #pragma unroll
    for (int t = 0; t < 16; t++) {
        int idx = tid + t * 256;
        int dd = idx & 63, ii = idx >> 6;
        Qs[dd][ii] = d_qh[(bh * NPOS + i0 + ii) * DHEAD + dd];
    }
    if (tid < 64) {
        int ig = bh * NPOS + i0 + tid;
        s_qm[tid][0] = d_qm[ig * 2];
        s_qm[tid][1] = d_qm[ig * 2 + 1];
        s_mmax[tid] = d_mmax[ig];
        s_minv[tid] = 1.0f / d_msum[ig];
        #pragma unroll
        for (int t = 0; t < 4; t++) s_top[tid][t] = d_top4[ig * 4 + t];
    }
    __syncthreads();

    float run_max[4], run_sum[4];
    #pragma unroll
    for (int r = 0; r < 4; r++) { run_max[r] = -CUDART_INF_F; run_sum[r] = 0.f; }
    u64r accp[2][4];
    #pragma unroll
    for (int c = 0; c < 4; c++) { accp[0][c] = 0ull; accp[1][c] = 0ull; }

    for (int j0 = 0; j0 < NPOS; j0 += 32) {
        #pragma unroll
        for (int t = 0; t < 8; t++) {
            int idx = tid + t * 256;
            int dd = idx & 63, jj = idx >> 6;
            Ks[dd][jj] = d_kh[(bh * NPOS + j0 + jj) * DHEAD + dd];
            Vs[jj][dd] = d_vh[(bh * NPOS + j0 + jj) * DHEAD + dd];
        }
        __syncthreads();

        u64r q00 = 0ull, q01 = 0ull, q10 = 0ull, q11 = 0ull;
        #pragma unroll
        for (int dd = 0; dd < 64; dd++) {
            u64r a01 = *(const u64r*)&Qs[dd][ty * 4];
            u64r a23 = *(const u64r*)&Qs[dd][ty * 4 + 2];
            float b0 = Ks[dd][tx * 2];
            float b1 = Ks[dd][tx * 2 + 1];
            u64r bb0 = pk2(b0, b0);
            u64r bb1 = pk2(b1, b1);
            ffma2(q00, a01, bb0);
            ffma2(q01, a01, bb1);
            ffma2(q10, a23, bb0);
            ffma2(q11, a23, bb1);
        }
        float sv[8];
        upk2(q00, sv[0], sv[2]);
        upk2(q01, sv[1], sv[3]);
        upk2(q10, sv[4], sv[6]);
        upk2(q11, sv[5], sv[7]);

        #pragma unroll
        for (int cq = 0; cq < 2; cq++) {
            int jg = j0 + tx * 2 + cq;
            float2 k2 = ((const float2*)d_km)[bh * NPOS + jg];
            #pragma unroll
            for (int r = 0; r < 4; r++) {
                int il = ty * 4 + r;
                float ml = mask_logit(s_qm[il][0], s_qm[il][1], k2.x, k2.y);
                float dprob = __expf(ml - s_mmax[il]) * s_minv[il];
                float oneh = (jg == s_top[il][0] || jg == s_top[il][1] ||
                              jg == s_top[il][2] || jg == s_top[il][3]) ? 1.0f : -100000.0f;
                float maskv = __fadd_rn(__fadd_rn(oneh, -dprob), dprob);
                sv[r * 2 + cq] = __fmul_rn(__fmul_rn(sv[r * 2 + cq], SCALE), maskv);
            }
        }

        float tm[4];
        #pragma unroll
        for (int r = 0; r < 4; r++) tm[r] = fmaxf(sv[r * 2], sv[r * 2 + 1]);
        #pragma unroll
        for (int off = 1; off < 16; off <<= 1) {
            #pragma unroll
            for (int r = 0; r < 4; r++)
                tm[r] = fmaxf(tm[r], __shfl_xor_sync(0xffffffffu, tm[r], off));
        }

        float fr[4];
        #pragma unroll
        for (int r = 0; r < 4; r++) {
            float nm = fmaxf(run_max[r], tm[r]);
            float f = __expf(run_max[r] - nm);
            run_max[r] = nm;
            fr[r] = f;
            float e0 = __expf(sv[r * 2] - nm);
            float e1 = __expf(sv[r * 2 + 1] - nm);
            run_sum[r] = run_sum[r] * f + e0 + e1;
            Es[tx * 2][ty * 4 + r]     = e0;
            Es[tx * 2 + 1][ty * 4 + r] = e1;
        }
        {
            u64r ff0 = pk2(fr[0], fr[1]);
            u64r ff1 = pk2(fr[2], fr[3]);
            #pragma unroll
            for (int c = 0; c < 4; c++) {
                accp[0][c] = fmul2(accp[0][c], ff0);
                accp[1][c] = fmul2(accp[1][c], ff1);
            }
        }
        __syncthreads();

        #pragma unroll
        for (int jj = 0; jj < 32; jj++) {
            u64r a01 = *(const u64r*)&Es[jj][ty * 4];
            u64r a23 = *(const u64r*)&Es[jj][ty * 4 + 2];
            #pragma unroll
            for (int c = 0; c < 4; c++) {
                float bvv = Vs[jj][tx * 4 + c];
                u64r bb = pk2(bvv, bvv);
                ffma2(accp[0][c], a01, bb);
                ffma2(accp[1][c], a23, bb);
            }
        }
        __syncthreads();
    }

    #pragma unroll
    for (int off = 1; off < 16; off <<= 1) {
        #pragma unroll
        for (int r = 0; r < 4; r++)
            run_sum[r] += __shfl_xor_sync(0xffffffffu, run_sum[r], off);
    }
    float ov[4][4];
    #pragma unroll
    for (int rp = 0; rp < 2; rp++)
        #pragma unroll
        for (int c = 0; c < 4; c++)
            upk2(accp[rp][c], ov[2 * rp][c], ov[2 * rp + 1][c]);

    int b = bh >> 3, h = bh & 7;
    #pragma unroll
    for (int r = 0; r < 4; r++) {
        int ii = i0 + ty * 4 + r;
        float inv = 1.0f / run_sum[r];
        float4 st;
        #pragma unroll
        for (int c = 0; c < 4; c++) ((float*)&st)[c] = ov[r][c] * inv;
        *(float4*)&d_ao[((size_t)(b * NPOS + ii)) * INNER + h * DHEAD + tx * 4] = st;
    }
}

// ---------------- output GEMM (FFMA2) ----------------
__global__ void k_out(const float* __restrict__ w, const float* __restrict__ ob, float* __restrict__ out) {
    __shared__ float As[32][68];
    __shared__ float Ws[32][68];
    int o0 = blockIdx.x * 64;
    int bi0 = blockIdx.y * 64;
    int tid = threadIdx.x;
    int ty = tid >> 4, tx = tid & 15;
    u64r accp[4][2];
    #pragma unroll
    for (int r = 0; r < 4; r++) { accp[r][0] = 0ull; accp[r][1] = 0ull; }
    for (int c0 = 0; c0 < INNER; c0 += 32) {
        #pragma unroll
        for (int t = 0; t < 8; t++) {
            int idx = tid + t * 256;
            int cc = idx & 31, ii = idx >> 5;
            As[cc][ii] = d_ao[(size_t)(bi0 + ii) * INNER + c0 + cc];
        }
        #pragma unroll
        for (int t = 0; t < 8; t++) {
            int idx = tid + t * 256;
            int cc = idx & 31, o = idx >> 5;
            Ws[cc][o] = w[(o0 + o) * INNER + c0 + cc];
        }
        __syncthreads();
        #pragma unroll
        for (int cc = 0; cc < 32; cc++) {
            u64r a01 = *(const u64r*)&As[cc][ty * 4];
            u64r a23 = *(const u64r*)&As[cc][ty * 4 + 2];
            #pragma unroll
            for (int r = 0; r < 4; r++) {
                float wv = Ws[cc][tx * 4 + r];
                u64r ww = pk2(wv, wv);
                ffma2(accp[r][0], a01, ww);
                ffma2(accp[r][1], a23, ww);
            }
        }
        __syncthreads();
    }
    #pragma unroll
    for (int r = 0; r < 4; r++) {
        int o = o0 + tx * 4 + r;
        float b0v, b1v, b2v, b3v;
        upk2(accp[r][0], b0v, b1v);
        upk2(accp[r][1], b2v, b3v);
        float bv[4] = {b0v, b1v, b2v, b3v};
        float obv = ob[o];
        #pragma unroll
        for (int q = 0; q < 4; q++) {
            int bi = bi0 + ty * 4 + q;
            out[(size_t)bi * DIM + o] = bv[q] + obv;
        }
    }
}

// ---------------- launch ----------------
extern "C" void kernel_launch(void* const* d_in, const int* in_sizes, int n_in,
                              void* d_out, int out_size) {
    const float* x     = (const float*)d_in[0];
    const float* qd_w  = (const float*)d_in[1];
    const float* qd_b  = (const float*)d_in[2];
    const float* q_g   = (const float*)d_in[3];
    const float* q_be  = (const float*)d_in[4];
    const float* qp_w  = (const float*)d_in[5];
    const float* qp_b  = (const float*)d_in[6];
    const float* qm_w  = (const float*)d_in[7];
    const float* qm_b  = (const float*)d_in[8];
    const float* kd_w  = (const float*)d_in[9];
    const float* kd_b  = (const float*)d_in[10];
    const float* k_g   = (const float*)d_in[11];
    const float* k_be  = (const float*)d_in[12];
    const float* kp_w  = (const float*)d_in[13];
    const float* kp_b  = (const float*)d_in[14];
    const float* km_w  = (const float*)d_in[15];
    const float* km_b  = (const float*)d_in[16];
    const float* vd_w  = (const float*)d_in[17];
    const float* vd_b  = (const float*)d_in[18];
    const float* v_g   = (const float*)d_in[19];
    const float* v_be  = (const float*)d_in[20];
    const float* vp_w  = (const float*)d_in[21];
    const float* vp_b  = (const float*)d_in[22];
    const float* out_w = (const float*)d_in[25];
    const float* out_b = (const float*)d_in[26];
    float* out = (float*)d_out;

    k_transpose<<<dim3(32, 8, 4), dim3(32, 8)>>>(x);
    k_meanmax<<<4096, 256>>>(x);
    k_maskconv<<<256, 256>>>(qm_w, qm_b, km_w, km_b);
    k_masktop<<<4096, 256>>>();

    k_sepconv<<<dim3(256, 3), 256>>>(qd_w, qd_b, q_g, q_be,
                                     kd_w, kd_b, k_g, k_be,
                                     vd_w, vd_b, v_g, v_be);
    k_pwgemm<<<dim3(16, 8, 12), 256>>>(qp_w, qp_b, kp_w, kp_b, vp_w, vp_b);

    k_attn<<<dim3(16, 32), 256>>>();
    k_out<<<dim3(4, 64), 256>>>(out_w, out_b, out);
}